// round 1
// baseline (speedup 1.0000x reference)
#include <cuda_runtime.h>

// fields: (B=64, H=512, W=512, C=6) float32
// pump_indices: (B, 2) int32
// out: (B, H, W, 4) float32  — per-sample mean of 5x5 window over channels [2:6],
//                              broadcast over the whole (H, W) plane.

#define H_DIM 512
#define W_DIM 512
#define C_DIM 6
#define RADIUS 2
#define WIN 5              // 2*RADIUS+1
#define WIN_PIX (WIN*WIN)  // 25
#define HW (H_DIM * W_DIM) // 262144 pixels per sample
#define MAX_B 128

__device__ float4 g_means[MAX_B];

// ---------------------------------------------------------------------------
// Kernel 1: one warp (one block of 32 threads) per sample.
// Lanes 0..24 each load the 4 channels of one window pixel; warp-reduce.
// ---------------------------------------------------------------------------
__global__ void compute_means_kernel(const float* __restrict__ fields,
                                     const int* __restrict__ pump_indices) {
    const int b = blockIdx.x;
    const int lane = threadIdx.x;

    const int py = pump_indices[2 * b + 0];
    const int px = pump_indices[2 * b + 1];

    float s0 = 0.f, s1 = 0.f, s2 = 0.f, s3 = 0.f;
    if (lane < WIN_PIX) {
        const int dy = lane / WIN;
        const int dx = lane % WIN;
        const int y = py - RADIUS + dy;
        const int x = px - RADIUS + dx;
        // channel offset 2 within a 6-float pixel -> 8-byte aligned, use 2x float2
        const float* p = fields + ((size_t)b * HW + (size_t)y * W_DIM + x) * C_DIM + 2;
        float2 a = *reinterpret_cast<const float2*>(p);
        float2 c = *reinterpret_cast<const float2*>(p + 2);
        s0 = a.x; s1 = a.y; s2 = c.x; s3 = c.y;
    }

    #pragma unroll
    for (int off = 16; off > 0; off >>= 1) {
        s0 += __shfl_down_sync(0xFFFFFFFFu, s0, off);
        s1 += __shfl_down_sync(0xFFFFFFFFu, s1, off);
        s2 += __shfl_down_sync(0xFFFFFFFFu, s2, off);
        s3 += __shfl_down_sync(0xFFFFFFFFu, s3, off);
    }

    if (lane == 0) {
        const float inv = 1.0f / (float)WIN_PIX;
        g_means[b] = make_float4(s0 * inv, s1 * inv, s2 * inv, s3 * inv);
    }
}

// ---------------------------------------------------------------------------
// Kernel 2: broadcast fill. Each output pixel = one float4 (4 channels).
// grid = (HW / (256*8), B), 256 threads, 8 float4 stores per thread.
// ---------------------------------------------------------------------------
#define FILL_THREADS 256
#define FILL_UNROLL 8

__global__ void __launch_bounds__(FILL_THREADS)
fill_kernel(float4* __restrict__ out) {
    const int b = blockIdx.y;
    const float4 m = g_means[b];

    float4* dst = out + (size_t)b * HW
                      + (size_t)blockIdx.x * (FILL_THREADS * FILL_UNROLL)
                      + threadIdx.x;
    #pragma unroll
    for (int i = 0; i < FILL_UNROLL; ++i) {
        dst[i * FILL_THREADS] = m;
    }
}

extern "C" void kernel_launch(void* const* d_in, const int* in_sizes, int n_in,
                              void* d_out, int out_size) {
    const float* fields = (const float*)d_in[0];
    const int* pump_indices = (const int*)d_in[1];
    float4* out = (float4*)d_out;

    const int B = in_sizes[1] / 2;  // (B, 2) int32

    compute_means_kernel<<<B, 32>>>(fields, pump_indices);

    dim3 grid(HW / (FILL_THREADS * FILL_UNROLL), B);
    fill_kernel<<<grid, FILL_THREADS>>>(out);
}